// round 10
// baseline (speedup 1.0000x reference)
#include <cuda_runtime.h>
#include <cuda.h>
#include <cuda_fp16.h>
#include <cstdint>
#include <cstddef>

// ============================================================================
// KAN layer as one 2:4-SPARSE fp16 GEMM (mma.sp.m16n8k32, sm_80+ portable):
// Exact reformulation (no pruning):
//   x = xc + r (r = x - clamp(x));  xc = -1 + sum_j 0.4j*hat_j;  sum hat_j = 1
//   out = A_sp @ W'^T + bias,  dense-K = 8 per input:
//   A cols [r, h1, h2, h3 | h4, h5, 0, 0]  -- each 4-group has <=2 nonzeros:
//     r!=0 => xc=+-1 => h1..h4=0; hats: only adjacent pair nonzero.
//   W' cols [bw, C1..C5, 0, 0], C_j = 0.4j*bw + (T_j - T0)
//   bias[o] = sum_i (T0[o,i] - bw[o,i])
// Compressed K = 4096 (was 6144 dense): -33% tensor work.
// Metadata layout guess: interleaved (lane c = k-half c; word = row g lo16,
// row g+8 hi16). Meta rides the TMA mbarrier via a uint64 tensor map.
// ============================================================================

#define INF_   1024
#define OUTF_  1024
#define MTOT   8192
#define KC     4096            // compressed K (4 per input)
#define KDN    8192            // dense K (8 per input)
#define BM     128
#define BN     128
#define BKC    64              // compressed K per iter
#define BKD    128             // dense K per iter (16 inputs)
#define KT     (KDN / BKD)     // 64
#define STG    2
#define ASZ    (BM * BKC * 2)  // 16384
#define BSZ    (BN * BKD * 2)  // 32768
#define MSZ    (BM * 16)       // 2048 (16 meta bytes per row per iter)
#define STAGEB (ASZ + BSZ + MSZ)            // 51200
#define HDR    1024
#define SMEMSZ (1024 + HDR + STG * STAGEB)  // pad + hdr + 100KB

__device__ __align__(1024) __half g_Ac[(size_t)MTOT * KC];          // 64 MB
__device__ __align__(1024) __half g_W[(size_t)OUTF_ * KDN];         // 16 MB
__device__ __align__(1024) unsigned char g_meta[(size_t)KT * MTOT * 16]; // 8 MB
__device__ float g_biasp[4096];
__device__ float g_bias[1024];

// ---------------------------------------------------------------------------
// helpers
// ---------------------------------------------------------------------------
__device__ __forceinline__ uint32_t s2u(const void* p) {
    uint32_t a;
    asm("{ .reg .u64 t; cvta.to.shared.u64 t, %1; cvt.u32.u64 %0, t; }"
        : "=r"(a) : "l"(p));
    return a;
}
__device__ __forceinline__ void mbar_init(uint32_t m, uint32_t c) {
    asm volatile("mbarrier.init.shared.b64 [%0], %1;" :: "r"(m), "r"(c) : "memory");
}
__device__ __forceinline__ void mbar_expect(uint32_t m, uint32_t bytes) {
    asm volatile("mbarrier.arrive.expect_tx.shared.b64 _, [%0], %1;"
                 :: "r"(m), "r"(bytes) : "memory");
}
__device__ __forceinline__ void mbar_wait(uint32_t m, uint32_t ph) {
    uint32_t done;
    do {
        asm volatile(
            "{\n\t.reg .pred p;\n\t"
            "mbarrier.try_wait.parity.acquire.cta.shared::cta.b64 p, [%1], %2, 0x989680;\n\t"
            "selp.b32 %0, 1, 0, p;\n\t}"
            : "=r"(done) : "r"(m), "r"(ph) : "memory");
    } while (!done);
}
__device__ __forceinline__ void tma2d(uint32_t dst, const CUtensorMap* m,
                                      int x, int y, uint32_t mbar) {
    asm volatile(
        "cp.async.bulk.tensor.2d.shared::cta.global.tile.mbarrier::complete_tx::bytes "
        "[%0], [%1, {%2, %3}], [%4];"
        :: "r"(dst), "l"(m), "r"(x), "r"(y), "r"(mbar) : "memory");
}
__device__ __forceinline__ void ldsm4(uint32_t* r, uint32_t a) {
    asm volatile("ldmatrix.sync.aligned.m8n8.x4.shared.b16 {%0,%1,%2,%3}, [%4];"
                 : "=r"(r[0]), "=r"(r[1]), "=r"(r[2]), "=r"(r[3]) : "r"(a));
}
__device__ __forceinline__ uint32_t lds_u16(uint32_t a) {
    uint32_t v;
    asm volatile("ld.shared.u16 %0, [%1];" : "=r"(v) : "r"(a));
    return v;
}
__device__ __forceinline__ void mmasp(float* c, const uint32_t* a,
                                      uint32_t b0, uint32_t b1, uint32_t b2,
                                      uint32_t b3, uint32_t e) {
    asm volatile(
        "mma.sp.sync.aligned.m16n8k32.row.col.f32.f16.f16.f32 "
        "{%0,%1,%2,%3}, {%4,%5,%6,%7}, {%8,%9,%10,%11}, {%0,%1,%2,%3}, %12, 0x0;"
        : "+f"(c[0]), "+f"(c[1]), "+f"(c[2]), "+f"(c[3])
        : "r"(a[0]), "r"(a[1]), "r"(a[2]), "r"(a[3]),
          "r"(b0), "r"(b1), "r"(b2), "r"(b3), "r"(e));
}

// ---------------------------------------------------------------------------
// build_A: one thread per (m,i). Compressed values [v0,v1,h4,h5] + meta byte.
//   interval j = clamp(floor((xc+1)*2.5), 0, 4)
//   j in {0,4}: keep (0,1)=(r,h1), nibble 4 ; j=1: (1,2)=(h1,h2), nibble 9 ;
//   j in {2,3}: keep (2,3)=(h2,h3), nibble 14. Group1 always (0,1)=(h4,h5).
// ---------------------------------------------------------------------------
__global__ void __launch_bounds__(256) build_A(const float* __restrict__ x) {
    __shared__ __half stc[256 * 4];
    __shared__ unsigned char stm[256];
    int tid = threadIdx.x;
    size_t p = (size_t)blockIdx.x * 256 + tid;
    float xv = x[p];
    float xc = fminf(fmaxf(xv, -1.0f), 1.0f);
    float r = xv - xc;
    int j = (int)((xc + 1.0f) * 2.5f);
    if (j > 4) j = 4;
    float h1 = fmaxf(0.0f, 1.0f - fabsf(xc + 0.6f) * 2.5f);
    float h2 = fmaxf(0.0f, 1.0f - fabsf(xc + 0.2f) * 2.5f);
    float h3 = fmaxf(0.0f, 1.0f - fabsf(xc - 0.2f) * 2.5f);
    float h4 = fmaxf(0.0f, 1.0f - fabsf(xc - 0.6f) * 2.5f);
    float h5 = fmaxf(0.0f, 1.0f - fabsf(xc - 1.0f) * 2.5f);
    float v0, v1;
    int n0;
    if (j == 0 || j == 4) { v0 = r;  v1 = h1; n0 = 4;  }
    else if (j == 1)      { v0 = h1; v1 = h2; n0 = 9;  }
    else                  { v0 = h2; v1 = h3; n0 = 14; }
    stc[tid * 4 + 0] = __float2half_rn(v0);
    stc[tid * 4 + 1] = __float2half_rn(v1);
    stc[tid * 4 + 2] = __float2half_rn(h4);
    stc[tid * 4 + 3] = __float2half_rn(h5);
    stm[tid] = (unsigned char)(n0 | 0x40);   // group1 nibble = 4
    __syncthreads();
    // compressed values: contiguous 2KB at g_Ac + p0*4
    size_t p0 = (size_t)blockIdx.x * 256;
    uint4* dstc = reinterpret_cast<uint4*>(g_Ac + p0 * 4);
    const uint4* srcc = reinterpret_cast<const uint4*>(stc);
    if (tid < 128) dstc[tid] = srcc[tid];
    // meta: layout g_meta[it][m][16], it = i/16. Block = 256 consecutive i
    // within one m -> 16 it-chunks of 16 bytes.
    if (tid < 16) {
        int m   = (int)(p0 >> 10);
        int it0 = (int)((p0 & 1023) >> 4);
        uint4* dstm = reinterpret_cast<uint4*>(
            g_meta + (size_t)(it0 + tid) * (MTOT * 16) + (size_t)m * 16);
        *dstm = reinterpret_cast<const uint4*>(stm)[tid];
    }
}

// ---------------------------------------------------------------------------
// build_W: one thread per (o,i). Emits [bw, C1..C5, 0, 0]; reduces T0-bw.
// ---------------------------------------------------------------------------
__global__ void __launch_bounds__(256) build_W(const float* __restrict__ sw,
                                               const float* __restrict__ bw) {
    __shared__ __half st[256 * 8];
    __shared__ float red[256];
    int tid = threadIdx.x;
    size_t p = (size_t)blockIdx.x * 256 + tid;
    const float4* s4 = reinterpret_cast<const float4*>(sw + p * 12);
    float4 a = s4[0], b = s4[1], c = s4[2];
    float bwv = bw[p];
    float T0 = a.x + a.y + a.z + a.w;
    float T5 = c.x + c.y + c.z + c.w;
    st[tid * 8 + 0] = __float2half_rn(bwv);
    st[tid * 8 + 1] = __float2half_rn(0.4f * bwv + (b.x - T0));
    st[tid * 8 + 2] = __float2half_rn(0.8f * bwv + (b.y - T0));
    st[tid * 8 + 3] = __float2half_rn(1.2f * bwv + (b.z - T0));
    st[tid * 8 + 4] = __float2half_rn(1.6f * bwv + (b.w - T0));
    st[tid * 8 + 5] = __float2half_rn(2.0f * bwv + (T5 - T0));
    st[tid * 8 + 6] = __half(0.0f);
    st[tid * 8 + 7] = __half(0.0f);
    red[tid] = T0 - bwv;
    __syncthreads();
    #pragma unroll
    for (int s = 128; s > 0; s >>= 1) {
        if (tid < s) red[tid] += red[tid + s];
        __syncthreads();
    }
    if (tid == 0) g_biasp[blockIdx.x] = red[0];
    uint4* dst = reinterpret_cast<uint4*>(g_W + (size_t)blockIdx.x * 256 * 8);
    const uint4* src = reinterpret_cast<const uint4*>(st);
    dst[tid] = src[tid];   // 256 uint4 = 4KB
}

__global__ void sum_bias() {
    int o = blockIdx.x * 256 + threadIdx.x;
    g_bias[o] = g_biasp[o * 4] + g_biasp[o * 4 + 1]
              + g_biasp[o * 4 + 2] + g_biasp[o * 4 + 3];
}

// ---------------------------------------------------------------------------
// Sparse GEMM: out = A_sp(8192 x 4096c/8192d) @ W'(1024 x 8192)^T + bias.
// CTA 128x128, 2-stage TMA ring (A comp + 2x B halves + meta via one mbar),
// 8 warps 2Mx4N, warp tile 64x32, mma.sp.m16n8k32, 2 CTAs/SM.
// ---------------------------------------------------------------------------
__global__ void __launch_bounds__(256, 2) kan_gemm_sp(
        const __grid_constant__ CUtensorMap tmA,
        const __grid_constant__ CUtensorMap tmB,
        const __grid_constant__ CUtensorMap tmM,
        float* __restrict__ out) {
    extern __shared__ unsigned char smem[];
    uint32_t sbA = (s2u(smem) + 1023u) & ~1023u;
    uint32_t SD = sbA + HDR;
    int tid = threadIdx.x;
    int wid = tid >> 5, lid = tid & 31;
    int n0 = blockIdx.x * BN;
    int m0 = blockIdx.y * BM;

    if (tid == 0) {
        mbar_init(sbA + 0, 1);
        mbar_init(sbA + 8, 1);
    }
    __syncthreads();
    if (tid == 0) {
        #pragma unroll
        for (int s = 0; s < 2; s++) {
            uint32_t fm = sbA + 8 * s;
            uint32_t ds = SD + s * STAGEB;
            mbar_expect(fm, STAGEB);
            tma2d(ds,                &tmA, s * BKC,      m0,     fm);
            tma2d(ds + ASZ,          &tmB, s * BKD,      n0,     fm);
            tma2d(ds + ASZ + 16384,  &tmB, s * BKD + 64, n0,     fm);
            tma2d(ds + ASZ + BSZ,    &tmM, m0 * 2,       s,      fm);
        }
    }

    int wm = (wid >> 2) * 64;      // 2 M warp-groups
    int wn = (wid & 3) * 32;       // 4 N warp-groups
    int mi = lid >> 3;
    int lr = lid & 7;
    uint32_t c2 = ((lid & 3) & 1) * 2;   // k-half byte offset for meta

    float acc[4][4][4] = {};

    for (int it = 0; it < KT; ++it) {
        __syncthreads();           // readers of stage being refilled are done
        if (tid == 0 && it >= 1 && it + 1 < KT) {
            int nx = it + 1;
            int s = nx & 1;
            uint32_t fm = sbA + 8 * s;
            uint32_t ds = SD + s * STAGEB;
            mbar_expect(fm, STAGEB);
            tma2d(ds,               &tmA, nx * BKC,      m0, fm);
            tma2d(ds + ASZ,         &tmB, nx * BKD,      n0, fm);
            tma2d(ds + ASZ + 16384, &tmB, nx * BKD + 64, n0, fm);
            tma2d(ds + ASZ + BSZ,   &tmM, m0 * 2,        nx, fm);
        }
        mbar_wait(sbA + 8 * (it & 1), (it >> 1) & 1);

        uint32_t asB = SD + (it & 1) * STAGEB;
        uint32_t bsB = asB + ASZ;
        uint32_t mtB = asB + ASZ + BSZ;

        #pragma unroll
        for (int kk = 0; kk < 4; ++kk) {
            uint32_t aF[4][4], bF[2][2][4], eW[4];
            #pragma unroll
            for (int a = 0; a < 4; a++) {          // compressed A, ck16 step
                int mr = wm + a * 16 + lr + (mi & 1) * 8;
                int kc = kk * 2 + (mi >> 1);
                ldsm4(aF[a], asB + mr * 128 + ((kc ^ (mr & 7)) << 4));
            }
            #pragma unroll
            for (int q = 0; q < 2; q++)            // dense B, two k16 halves
                #pragma unroll
                for (int hh = 0; hh < 2; hh++) {
                    int kh = kk * 2 + hh;          // 0..7
                    int sub = kh >> 2;
                    int kc = (kh & 3) * 2 + (mi & 1);
                    int nr = wn + q * 16 + ((mi >> 1) << 3) + lr;
                    ldsm4(bF[q][hh],
                          bsB + sub * 16384 + nr * 128 + ((kc ^ (nr & 7)) << 4));
                }
            #pragma unroll
            for (int a = 0; a < 4; a++) {          // metadata words
                int rl = wm + a * 16 + (lid >> 2);
                uint32_t lo = lds_u16(mtB + rl * 16 + kk * 4 + c2);
                uint32_t hi = lds_u16(mtB + rl * 16 + 128 + kk * 4 + c2);
                eW[a] = lo | (hi << 16);
            }
            #pragma unroll
            for (int a = 0; a < 4; a++)
                #pragma unroll
                for (int b = 0; b < 4; b++) {
                    int q = b >> 1, o2 = (b & 1) * 2;
                    mmasp(acc[a][b], aF[a],
                          bF[q][0][o2], bF[q][0][o2 + 1],
                          bF[q][1][o2], bF[q][1][o2 + 1], eW[a]);
                }
        }
    }

    // epilogue: add fp32 bias, store fp32 tiles
    int row0 = m0 + wm + (lid >> 2);
    int col0 = n0 + wn + (lid & 3) * 2;
    #pragma unroll
    for (int b = 0; b < 4; b++) {
        float bv0 = g_bias[col0 + b * 8];
        float bv1 = g_bias[col0 + b * 8 + 1];
        #pragma unroll
        for (int a = 0; a < 4; a++) {
            float* p0 = out + (size_t)(row0 + a * 16) * OUTF_ + col0 + b * 8;
            float* p1 = p0 + (size_t)8 * OUTF_;
            *reinterpret_cast<float2*>(p0) =
                make_float2(acc[a][b][0] + bv0, acc[a][b][1] + bv1);
            *reinterpret_cast<float2*>(p1) =
                make_float2(acc[a][b][2] + bv0, acc[a][b][3] + bv1);
        }
    }
}

// ---------------------------------------------------------------------------
typedef CUresult (CUDAAPI *PFN_tmEncode)(
    CUtensorMap*, CUtensorMapDataType, cuuint32_t, void*,
    const cuuint64_t*, const cuuint64_t*, const cuuint32_t*, const cuuint32_t*,
    CUtensorMapInterleave, CUtensorMapSwizzle, CUtensorMapL2promotion,
    CUtensorMapFloatOOBfill);

extern "C" void kernel_launch(void* const* d_in, const int* in_sizes, int n_in,
                              void* d_out, int out_size) {
    const float* x  = (const float*)d_in[0];   // (4,2048,1024)
    const float* sw = (const float*)d_in[1];   // (1024,1024,12)
    const float* bw = (const float*)d_in[2];   // (1024,1024)
    float* out = (float*)d_out;                // (4,2048,1024)

    CUtensorMap tmA, tmB, tmM;
    PFN_tmEncode enc = nullptr;
    cudaDriverEntryPointQueryResult qr = cudaDriverEntryPointSymbolNotFound;
    cudaGetDriverEntryPoint("cuTensorMapEncodeTiled", (void**)&enc,
                            cudaEnableDefault, &qr);
    void *pA = nullptr, *pW = nullptr, *pM = nullptr;
    cudaGetSymbolAddress(&pA, g_Ac);
    cudaGetSymbolAddress(&pW, g_W);
    cudaGetSymbolAddress(&pM, g_meta);

    cuuint64_t dimsA[2] = {KC, MTOT};
    cuuint64_t strA[1]  = {KC * 2};
    cuuint32_t boxA[2]  = {BKC, BM};
    cuuint32_t el[2]    = {1, 1};
    enc(&tmA, CU_TENSOR_MAP_DATA_TYPE_FLOAT16, 2, pA, dimsA, strA, boxA, el,
        CU_TENSOR_MAP_INTERLEAVE_NONE, CU_TENSOR_MAP_SWIZZLE_128B,
        CU_TENSOR_MAP_L2_PROMOTION_L2_128B, CU_TENSOR_MAP_FLOAT_OOB_FILL_NONE);

    cuuint64_t dimsB[2] = {KDN, OUTF_};
    cuuint64_t strB[1]  = {KDN * 2};
    cuuint32_t boxB[2]  = {64, BN};
    enc(&tmB, CU_TENSOR_MAP_DATA_TYPE_FLOAT16, 2, pW, dimsB, strB, boxB, el,
        CU_TENSOR_MAP_INTERLEAVE_NONE, CU_TENSOR_MAP_SWIZZLE_128B,
        CU_TENSOR_MAP_L2_PROMOTION_L2_128B, CU_TENSOR_MAP_FLOAT_OOB_FILL_NONE);

    // meta as uint64 2D: [it rows][m*2 u64 cols], box = 256 u64 = 128 m-rows
    cuuint64_t dimsM[2] = {MTOT * 2, KT};
    cuuint64_t strM[1]  = {(cuuint64_t)MTOT * 16};
    cuuint32_t boxM[2]  = {256, 1};
    enc(&tmM, CU_TENSOR_MAP_DATA_TYPE_UINT64, 2, pM, dimsM, strM, boxM, el,
        CU_TENSOR_MAP_INTERLEAVE_NONE, CU_TENSOR_MAP_SWIZZLE_NONE,
        CU_TENSOR_MAP_L2_PROMOTION_L2_128B, CU_TENSOR_MAP_FLOAT_OOB_FILL_NONE);

    cudaFuncSetAttribute(kan_gemm_sp, cudaFuncAttributeMaxDynamicSharedMemorySize, SMEMSZ);

    build_W<<<(OUTF_ * INF_) / 256, 256>>>(sw, bw);
    sum_bias<<<4, 256>>>();
    build_A<<<(MTOT * INF_) / 256, 256>>>(x);
    dim3 grid(OUTF_ / BN, MTOT / BM);   // x = N tile (fast) -> A L2 reuse
    kan_gemm_sp<<<grid, 256, SMEMSZ>>>(tmA, tmB, tmM, out);
}

// round 12
// speedup vs baseline: 7.5891x; 7.5891x over previous
#include <cuda_runtime.h>
#include <cuda.h>
#include <cuda_fp16.h>
#include <cstdint>
#include <cstddef>

// ============================================================================
// KAN layer as one fp16 dense GEMM (portable sm_100 path: TMA + ldmatrix +
// mma.sync.m16n8k16). R10 proved mma.sp is ALU-emulated on this target; dense
// is the fast path.
//   out[m,o] = x@bw^T + sum_j hat_j(clamp(x)) T_j  (12-knot basis -> 6 knots)
// Partition of unity (sum hat_j = 1) -> T0 becomes a per-o fp32 bias, K=6/input:
// A: (8192 x 6144) fp16 [x, hat1..hat5] ; W: (1024 x 6144) [bw, T1-T0..T5-T0]
// R12: producer/consumer decoupling (R11) with the mbarrier-init ordering
// fixed: init + TMA issue in the SAME thread (tid 256) + fence.proxy.async
// before first TMA, so the async proxy never sees a stale barrier word.
// Per-stage full/empty mbarriers, no CTA barrier in the mainloop. 2 CTAs/SM.
// ============================================================================

#define INF_   1024
#define OUTF_  1024
#define MTOT   8192
#define KD     6144            // 6 * 1024
#define BM     128
#define BN     128
#define BK     64
#define KT     (KD / BK)       // 96
#define STG    3
#define ASZ    (BM * BK * 2)   // 16384
#define BSZ    (BN * BK * 2)   // 16384
#define STAGEB (ASZ + BSZ)     // 32768
#define HDR    1024
#define SMEMSZ (1024 + HDR + STG * STAGEB)

__device__ __align__(1024) __half g_A[(size_t)MTOT * KD];   // 96 MB
__device__ __align__(1024) __half g_W[(size_t)OUTF_ * KD];  // 12 MB
__device__ float g_biasp[4096];
__device__ float g_bias[1024];

// ---------------------------------------------------------------------------
// helpers
// ---------------------------------------------------------------------------
__device__ __forceinline__ uint32_t s2u(const void* p) {
    uint32_t a;
    asm("{ .reg .u64 t; cvta.to.shared.u64 t, %1; cvt.u32.u64 %0, t; }"
        : "=r"(a) : "l"(p));
    return a;
}
__device__ __forceinline__ void mbar_init(uint32_t m, uint32_t c) {
    asm volatile("mbarrier.init.shared.b64 [%0], %1;" :: "r"(m), "r"(c) : "memory");
}
__device__ __forceinline__ void fence_async_proxy() {
    asm volatile("fence.proxy.async.shared::cta;" ::: "memory");
}
__device__ __forceinline__ void mbar_expect(uint32_t m, uint32_t bytes) {
    asm volatile("mbarrier.arrive.expect_tx.shared.b64 _, [%0], %1;"
                 :: "r"(m), "r"(bytes) : "memory");
}
__device__ __forceinline__ void mbar_arrive(uint32_t m) {
    asm volatile("mbarrier.arrive.shared.b64 _, [%0];" :: "r"(m) : "memory");
}
__device__ __forceinline__ void mbar_wait(uint32_t m, uint32_t ph) {
    uint32_t done;
    do {
        asm volatile(
            "{\n\t.reg .pred p;\n\t"
            "mbarrier.try_wait.parity.acquire.cta.shared::cta.b64 p, [%1], %2, 0x989680;\n\t"
            "selp.b32 %0, 1, 0, p;\n\t}"
            : "=r"(done) : "r"(m), "r"(ph) : "memory");
    } while (!done);
}
__device__ __forceinline__ void tma2d(uint32_t dst, const CUtensorMap* m,
                                      int x, int y, uint32_t mbar) {
    asm volatile(
        "cp.async.bulk.tensor.2d.shared::cta.global.tile.mbarrier::complete_tx::bytes "
        "[%0], [%1, {%2, %3}], [%4];"
        :: "r"(dst), "l"(m), "r"(x), "r"(y), "r"(mbar) : "memory");
}
__device__ __forceinline__ void ldsm4(uint32_t* r, uint32_t a) {
    asm volatile("ldmatrix.sync.aligned.m8n8.x4.shared.b16 {%0,%1,%2,%3}, [%4];"
                 : "=r"(r[0]), "=r"(r[1]), "=r"(r[2]), "=r"(r[3]) : "r"(a));
}
__device__ __forceinline__ void mma16816(float* c, const uint32_t* a, const uint32_t* b) {
    asm volatile(
        "mma.sync.aligned.m16n8k16.row.col.f32.f16.f16.f32 "
        "{%0,%1,%2,%3}, {%4,%5,%6,%7}, {%8,%9}, {%0,%1,%2,%3};"
        : "+f"(c[0]), "+f"(c[1]), "+f"(c[2]), "+f"(c[3])
        : "r"(a[0]), "r"(a[1]), "r"(a[2]), "r"(a[3]), "r"(b[0]), "r"(b[1]));
}

// ---------------------------------------------------------------------------
// build_AW: fused prologue. Blocks [0,4096) build W (+ T0 partial reduce),
// blocks [4096, 36864) build A. One thread per (row, i) pair in each.
// ---------------------------------------------------------------------------
__global__ void __launch_bounds__(256) build_AW(const float* __restrict__ x,
                                                const float* __restrict__ sw,
                                                const float* __restrict__ bw) {
    __shared__ __half st[256 * 6];
    __shared__ float red[256];
    int tid = threadIdx.x;
    if (blockIdx.x < 4096) {
        // ----- W path -----
        size_t p = (size_t)blockIdx.x * 256 + tid;
        const float4* s4 = reinterpret_cast<const float4*>(sw + p * 12);
        float4 a = s4[0], b = s4[1], c = s4[2];
        float T0 = a.x + a.y + a.z + a.w;
        float T5 = c.x + c.y + c.z + c.w;
        st[tid * 6 + 0] = __float2half_rn(bw[p]);
        st[tid * 6 + 1] = __float2half_rn(b.x - T0);
        st[tid * 6 + 2] = __float2half_rn(b.y - T0);
        st[tid * 6 + 3] = __float2half_rn(b.z - T0);
        st[tid * 6 + 4] = __float2half_rn(b.w - T0);
        st[tid * 6 + 5] = __float2half_rn(T5 - T0);
        red[tid] = T0;
        __syncthreads();
        #pragma unroll
        for (int s = 128; s > 0; s >>= 1) {
            if (tid < s) red[tid] += red[tid + s];
            __syncthreads();
        }
        if (tid == 0) g_biasp[blockIdx.x] = red[0];
        uint4* dst = reinterpret_cast<uint4*>(
            reinterpret_cast<char*>(g_W) + (size_t)blockIdx.x * 3072);
        const uint4* src = reinterpret_cast<const uint4*>(st);
        if (tid < 192) dst[tid] = src[tid];
    } else {
        // ----- A path -----
        int bid = blockIdx.x - 4096;
        size_t p = (size_t)bid * 256 + tid;
        float xv = x[p];
        float xc = fminf(fmaxf(xv, -1.0f), 1.0f);
        st[tid * 6] = __float2half_rn(xv);
        #pragma unroll
        for (int j = 1; j <= 5; j++) {
            float knot = 0.4f * (float)j - 1.0f;
            float h = fmaxf(0.0f, 1.0f - fabsf(xc - knot) * 2.5f);
            st[tid * 6 + j] = __float2half_rn(h);
        }
        __syncthreads();
        uint4* dst = reinterpret_cast<uint4*>(
            reinterpret_cast<char*>(g_A) + (size_t)bid * 3072);
        const uint4* src = reinterpret_cast<const uint4*>(st);
        if (tid < 192) dst[tid] = src[tid];
    }
}

__global__ void sum_bias() {
    int o = blockIdx.x * 256 + threadIdx.x;
    g_bias[o] = g_biasp[o * 4] + g_biasp[o * 4 + 1]
              + g_biasp[o * 4 + 2] + g_biasp[o * 4 + 3];
}

// ---------------------------------------------------------------------------
// GEMM: out = A(8192x6144) @ W(1024x6144)^T + bias, fp16 in, fp32 reg accum.
// 288 threads: warps 0-7 consume (2Mx4N, warp tile 64x32), warp 8 produces.
// Per-stage mbarriers: full[s] (TMA tx, count 1) at sbA+8s; empty[s]
// (8 consumer-warp arrivals) at sbA+32+8s. No CTA barrier in the mainloop.
// blockIdx.x = N tile (fast) so concurrent CTAs share the A tile in L2.
// ---------------------------------------------------------------------------
__global__ void __launch_bounds__(288, 2) kan_gemm(
        const __grid_constant__ CUtensorMap tmA,
        const __grid_constant__ CUtensorMap tmB,
        float* __restrict__ out) {
    extern __shared__ unsigned char smem[];
    uint32_t sbA = (s2u(smem) + 1023u) & ~1023u;
    uint32_t SD = sbA + HDR;
    int tid = threadIdx.x;
    int wid = tid >> 5, lid = tid & 31;
    int n0 = blockIdx.x * BN;
    int m0 = blockIdx.y * BM;

    // init by the SAME thread that issues the TMAs (async-proxy ordering),
    // then fence + CTA barrier before anyone uses the barriers.
    if (tid == 256) {
        #pragma unroll
        for (int s = 0; s < STG; s++) {
            mbar_init(sbA + 8 * s, 1);        // full
            mbar_init(sbA + 32 + 8 * s, 8);   // empty: 8 consumer warps
        }
        fence_async_proxy();
    }
    __syncthreads();

    if (tid == 256) {
        // ---------------- producer (lane 0 of warp 8) ----------------
        #pragma unroll
        for (int s = 0; s < STG; s++) {       // rounds 0..2: no empty wait
            uint32_t fm = sbA + 8 * s;
            uint32_t ds = SD + s * STAGEB;
            mbar_expect(fm, STAGEB);
            tma2d(ds,       &tmA, s * BK, m0, fm);
            tma2d(ds + ASZ, &tmB, s * BK, n0, fm);
        }
        int s = 0, er = 0;                    // empty parity cursor
        for (int itp = STG; itp < KT; ++itp) {
            mbar_wait(sbA + 32 + 8 * s, er);  // consumers released round r-1
            uint32_t fm = sbA + 8 * s;
            uint32_t ds = SD + s * STAGEB;
            mbar_expect(fm, STAGEB);
            tma2d(ds,       &tmA, itp * BK, m0, fm);
            tma2d(ds + ASZ, &tmB, itp * BK, n0, fm);
            if (++s == STG) { s = 0; er ^= 1; }
        }
    } else if (wid < 8) {
        // ---------------- consumers: free-running ----------------
        int wm = (wid >> 2) * 64;
        int wn = (wid & 3) * 32;
        int mi = lid >> 3;
        int lr = lid & 7;

        float acc[4][4][4] = {};

        int s = 0, ph = 0;
        for (int it = 0; it < KT; ++it) {
            mbar_wait(sbA + 8 * s, ph);
            uint32_t asB = SD + s * STAGEB;
            uint32_t bsB = asB + ASZ;
            #pragma unroll
            for (int ks = 0; ks < 4; ++ks) {
                uint32_t aF[4][4], bF[2][4];
                #pragma unroll
                for (int a = 0; a < 4; a++) {
                    int mr = wm + a * 16 + lr + (mi & 1) * 8;
                    int kc = ks * 2 + (mi >> 1);
                    ldsm4(aF[a], asB + mr * 128 + ((kc ^ (mr & 7)) << 4));
                }
                #pragma unroll
                for (int q = 0; q < 2; q++) {
                    int nr = wn + q * 16 + ((mi >> 1) << 3) + lr;
                    int kc = ks * 2 + (mi & 1);
                    ldsm4(bF[q], bsB + nr * 128 + ((kc ^ (nr & 7)) << 4));
                }
                #pragma unroll
                for (int a = 0; a < 4; a++)
                    #pragma unroll
                    for (int b = 0; b < 4; b++)
                        mma16816(acc[a][b], aF[a], &bF[b >> 1][(b & 1) * 2]);
            }
            __syncwarp();
            if (lid == 0) mbar_arrive(sbA + 32 + 8 * s);
            if (++s == STG) { s = 0; ph ^= 1; }
        }

        // epilogue: per-warp, no CTA sync needed
        int row0 = m0 + wm + (lid >> 2);
        int col0 = n0 + wn + (lid & 3) * 2;
        #pragma unroll
        for (int b = 0; b < 4; b++) {
            float bv0 = g_bias[col0 + b * 8];
            float bv1 = g_bias[col0 + b * 8 + 1];
            #pragma unroll
            for (int a = 0; a < 4; a++) {
                float* p0 = out + (size_t)(row0 + a * 16) * OUTF_ + col0 + b * 8;
                float* p1 = p0 + (size_t)8 * OUTF_;
                *reinterpret_cast<float2*>(p0) =
                    make_float2(acc[a][b][0] + bv0, acc[a][b][1] + bv1);
                *reinterpret_cast<float2*>(p1) =
                    make_float2(acc[a][b][2] + bv0, acc[a][b][3] + bv1);
            }
        }
    }
}

// ---------------------------------------------------------------------------
typedef CUresult (CUDAAPI *PFN_tmEncode)(
    CUtensorMap*, CUtensorMapDataType, cuuint32_t, void*,
    const cuuint64_t*, const cuuint64_t*, const cuuint32_t*, const cuuint32_t*,
    CUtensorMapInterleave, CUtensorMapSwizzle, CUtensorMapL2promotion,
    CUtensorMapFloatOOBfill);

extern "C" void kernel_launch(void* const* d_in, const int* in_sizes, int n_in,
                              void* d_out, int out_size) {
    const float* x  = (const float*)d_in[0];   // (4,2048,1024)
    const float* sw = (const float*)d_in[1];   // (1024,1024,12)
    const float* bw = (const float*)d_in[2];   // (1024,1024)
    float* out = (float*)d_out;                // (4,2048,1024)

    CUtensorMap tmA, tmB;
    PFN_tmEncode enc = nullptr;
    cudaDriverEntryPointQueryResult qr = cudaDriverEntryPointSymbolNotFound;
    cudaGetDriverEntryPoint("cuTensorMapEncodeTiled", (void**)&enc,
                            cudaEnableDefault, &qr);
    void *pA = nullptr, *pW = nullptr;
    cudaGetSymbolAddress(&pA, g_A);
    cudaGetSymbolAddress(&pW, g_W);

    cuuint64_t dimsA[2] = {KD, MTOT};
    cuuint64_t strA[1]  = {KD * 2};
    cuuint32_t boxA[2]  = {BK, BM};
    cuuint32_t el[2]    = {1, 1};
    enc(&tmA, CU_TENSOR_MAP_DATA_TYPE_FLOAT16, 2, pA, dimsA, strA, boxA, el,
        CU_TENSOR_MAP_INTERLEAVE_NONE, CU_TENSOR_MAP_SWIZZLE_128B,
        CU_TENSOR_MAP_L2_PROMOTION_L2_128B, CU_TENSOR_MAP_FLOAT_OOB_FILL_NONE);

    cuuint64_t dimsB[2] = {KD, OUTF_};
    cuuint64_t strB[1]  = {KD * 2};
    cuuint32_t boxB[2]  = {BK, BN};
    enc(&tmB, CU_TENSOR_MAP_DATA_TYPE_FLOAT16, 2, pW, dimsB, strB, boxB, el,
        CU_TENSOR_MAP_INTERLEAVE_NONE, CU_TENSOR_MAP_SWIZZLE_128B,
        CU_TENSOR_MAP_L2_PROMOTION_L2_128B, CU_TENSOR_MAP_FLOAT_OOB_FILL_NONE);

    cudaFuncSetAttribute(kan_gemm, cudaFuncAttributeMaxDynamicSharedMemorySize, SMEMSZ);

    build_AW<<<4096 + (MTOT * INF_) / 256, 256>>>(x, sw, bw);
    sum_bias<<<4, 256>>>();
    dim3 grid(OUTF_ / BN, MTOT / BM);   // x = N tile (fast) -> A L2 reuse
    kan_gemm<<<grid, 288, SMEMSZ>>>(tmA, tmB, out);
}